// round 12
// baseline (speedup 1.0000x reference)
#include <cuda_runtime.h>
#include <math.h>

// Shapes fixed by the problem instance.
#define B_SZ 2048
#define P_SZ 4
#define N_SZ 128
#define D_SZ 1024
#define S_SZ (N_SZ + 1)      // 129 samples: [last positive, negatives...]
#define EPS_F 1e-6f

#define THREADS 256
#define NWARP (THREADS / 32)

#define HALF0_END 65         // block h=0: samples [0,65); h=1: samples [65,129)
#define MAX_LOCAL 65

// Per-(batch, half) partials: {sum_exp(sim - 1), sim0 (h==0 only)}.
// Cosine similarity <= 1, so m = 1 is a valid global softmax shift:
// exp(sim-1) in [e^-2, 1] -- no overflow/underflow possible.
__device__ float2 g_part[B_SZ][2];

__global__ __launch_bounds__(THREADS)
void contrastive_sim_kernel(const float* __restrict__ anchor,
                            const float* __restrict__ positives,
                            const float* __restrict__ negatives) {
    const int b    = blockIdx.x;
    const int h    = blockIdx.y;
    const int tid  = threadIdx.x;
    const int warp = tid >> 5;
    const int lane = tid & 31;

    const int s_begin = h ? HALF0_END : 0;
    const int s_end   = h ? S_SZ : HALF0_END;
    const int n_local = s_end - s_begin;

    __shared__ float4 sa[D_SZ / 4];        // anchor row, 4 KB
    __shared__ float  sims[MAX_LOCAL];
    __shared__ float  red[NWARP];
    __shared__ float  s_na;

    // ---- load anchor into smem, accumulate ||a||^2 ----
    const float4* ap = reinterpret_cast<const float4*>(anchor + (size_t)b * D_SZ);
    float asq = 0.f;
    #pragma unroll
    for (int i = tid; i < D_SZ / 4; i += THREADS) {
        float4 v = ap[i];
        sa[i] = v;
        asq += v.x * v.x + v.y * v.y + v.z * v.z + v.w * v.w;
    }
    #pragma unroll
    for (int o = 16; o; o >>= 1) asq += __shfl_down_sync(0xffffffffu, asq, o);
    if (lane == 0) red[warp] = asq;
    __syncthreads();
    if (warp == 0) {
        float v = (lane < NWARP) ? red[lane] : 0.f;
        #pragma unroll
        for (int o = 16; o; o >>= 1) v += __shfl_down_sync(0xffffffffu, v, o);
        if (lane == 0) s_na = fmaxf(sqrtf(v), EPS_F);
    }
    __syncthreads();
    const float na = s_na;

    // ---- each warp: cosine sim for its share of this half's samples ----
    for (int s = s_begin + warp; s < s_end; s += NWARP) {
        const float4* xp;
        if (s == 0)
            xp = reinterpret_cast<const float4*>(
                positives + ((size_t)b * P_SZ + (P_SZ - 1)) * D_SZ);
        else
            xp = reinterpret_cast<const float4*>(
                negatives + ((size_t)b * N_SZ + (s - 1)) * D_SZ);

        float dot = 0.f, nsq = 0.f;
        #pragma unroll
        for (int i = 0; i < D_SZ / 4 / 32; i++) {   // 8 coalesced float4 loads/lane
            int idx = i * 32 + lane;
            float4 x = xp[idx];
            float4 a = sa[idx];
            dot += a.x * x.x + a.y * x.y + a.z * x.z + a.w * x.w;
            nsq += x.x * x.x + x.y * x.y + x.z * x.z + x.w * x.w;
        }
        #pragma unroll
        for (int o = 16; o; o >>= 1) {
            dot += __shfl_down_sync(0xffffffffu, dot, o);
            nsq += __shfl_down_sync(0xffffffffu, nsq, o);
        }
        if (lane == 0) {
            float ns = fmaxf(sqrtf(nsq), EPS_F);
            sims[s - s_begin] = dot / (na * ns);
        }
    }
    __syncthreads();

    // ---- warp 0: partial sum_exp with fixed shift m = 1 (sim <= 1) ----
    if (warp == 0) {
        float sum = 0.f;
        for (int s = lane; s < n_local; s += 32) sum += __expf(sims[s] - 1.0f);
        #pragma unroll
        for (int o = 16; o; o >>= 1) sum += __shfl_xor_sync(0xffffffffu, sum, o);
        if (lane == 0) {
            float sim0 = (h == 0) ? sims[0] : 0.f;
            g_part[b][h] = make_float2(sum, sim0);
        }
    }
}

__global__ __launch_bounds__(1024)
void contrastive_reduce_kernel(float* __restrict__ out) {
    const int tid  = threadIdx.x;
    const int warp = tid >> 5;
    const int lane = tid & 31;
    __shared__ float red[32];

    // Each thread handles exactly 2 batches: all loads issue up-front (high
    // MLP), MUFU chain depth 2 -- latency, not a serial 8-deep loop.
    float2 a0 = g_part[tid][0];
    float2 a1 = g_part[tid][1];
    float2 b0 = g_part[tid + 1024][0];
    float2 b1 = g_part[tid + 1024][1];

    float s = -(a0.y - 1.0f - __logf(a0.x + a1.x))
            + -(b0.y - 1.0f - __logf(b0.x + b1.x));

    #pragma unroll
    for (int o = 16; o; o >>= 1) s += __shfl_down_sync(0xffffffffu, s, o);
    if (lane == 0) red[warp] = s;
    __syncthreads();
    if (warp == 0) {
        float v = (lane < 32) ? red[lane] : 0.f;
        #pragma unroll
        for (int o = 16; o; o >>= 1) v += __shfl_down_sync(0xffffffffu, v, o);
        if (lane == 0) *out = v / (float)B_SZ;
    }
}

extern "C" void kernel_launch(void* const* d_in, const int* in_sizes, int n_in,
                              void* d_out, int out_size) {
    const float* anchor    = (const float*)d_in[0];
    const float* positives = (const float*)d_in[1];
    const float* negatives = (const float*)d_in[2];
    float* out = (float*)d_out;

    contrastive_sim_kernel<<<dim3(B_SZ, 2), THREADS>>>(anchor, positives, negatives);
    contrastive_reduce_kernel<<<1, 1024>>>(out);
}

// round 16
// speedup vs baseline: 1.0505x; 1.0505x over previous
#include <cuda_runtime.h>
#include <math.h>

// Shapes fixed by the problem instance.
#define B_SZ 2048
#define P_SZ 4
#define N_SZ 128
#define D_SZ 1024
#define S_SZ (N_SZ + 1)      // 129 samples: [last positive, negatives...]
#define EPS_F 1e-6f

#define THREADS 256
#define NWARP (THREADS / 32)

// Per-batch partials: {sum_exp(sim - 1), sim0}.
// Cosine similarity <= 1, so m = 1 is a valid global softmax shift:
// exp(sim - 1) in [e^-2, 1] -- no overflow/underflow possible.
__device__ float2 g_part[B_SZ];

__global__ __launch_bounds__(THREADS)
void contrastive_sim_kernel(const float* __restrict__ anchor,
                            const float* __restrict__ positives,
                            const float* __restrict__ negatives) {
    const int b    = blockIdx.x;
    const int tid  = threadIdx.x;
    const int warp = tid >> 5;
    const int lane = tid & 31;

    __shared__ float4 sa[D_SZ / 4];   // anchor row, 4 KB
    __shared__ float  red[NWARP];
    __shared__ float  s_na;
    __shared__ float  s_sim0;
    __shared__ float  wsum[NWARP];    // per-warp partial sum_exp

    // ---- load anchor into smem, accumulate ||a||^2 ----
    const float4* ap = reinterpret_cast<const float4*>(anchor + (size_t)b * D_SZ);
    float asq = 0.f;
    #pragma unroll
    for (int i = tid; i < D_SZ / 4; i += THREADS) {
        float4 v = ap[i];
        sa[i] = v;
        asq += v.x * v.x + v.y * v.y + v.z * v.z + v.w * v.w;
    }
    #pragma unroll
    for (int o = 16; o; o >>= 1) asq += __shfl_down_sync(0xffffffffu, asq, o);
    if (lane == 0) red[warp] = asq;
    __syncthreads();
    if (warp == 0) {
        float v = (lane < NWARP) ? red[lane] : 0.f;
        #pragma unroll
        for (int o = 16; o; o >>= 1) v += __shfl_down_sync(0xffffffffu, v, o);
        if (lane == 0) s_na = fmaxf(sqrtf(v), EPS_F);
    }
    __syncthreads();
    const float na = s_na;

    // ---- each warp: cosine sims for its samples; accumulate exp in regs ----
    float wexp = 0.f;   // lane-0 meaningful after each inner reduce
    for (int s = warp; s < S_SZ; s += NWARP) {
        const float4* xp;
        if (s == 0)
            xp = reinterpret_cast<const float4*>(
                positives + ((size_t)b * P_SZ + (P_SZ - 1)) * D_SZ);
        else
            xp = reinterpret_cast<const float4*>(
                negatives + ((size_t)b * N_SZ + (s - 1)) * D_SZ);

        float dot = 0.f, nsq = 0.f;
        #pragma unroll
        for (int i = 0; i < D_SZ / 4 / 32; i++) {   // 8 coalesced float4 loads/lane
            int idx = i * 32 + lane;
            float4 x = xp[idx];
            float4 a = sa[idx];
            dot += a.x * x.x + a.y * x.y + a.z * x.z + a.w * x.w;
            nsq += x.x * x.x + x.y * x.y + x.z * x.z + x.w * x.w;
        }
        #pragma unroll
        for (int o = 16; o; o >>= 1) {
            dot += __shfl_down_sync(0xffffffffu, dot, o);
            nsq += __shfl_down_sync(0xffffffffu, nsq, o);
        }
        if (lane == 0) {
            float ns  = fmaxf(sqrtf(nsq), EPS_F);
            float sim = dot / (na * ns);
            wexp += __expf(sim - 1.0f);
            if (s == 0) s_sim0 = sim;
        }
    }
    if (lane == 0) wsum[warp] = wexp;
    __syncthreads();

    // ---- warp 0: combine 8 per-warp partials, emit float2 ----
    if (warp == 0 && lane == 0) {
        float sum = 0.f;
        #pragma unroll
        for (int w = 0; w < NWARP; w++) sum += wsum[w];
        g_part[b] = make_float2(sum, s_sim0);
    }
}

__global__ __launch_bounds__(1024)
void contrastive_reduce_kernel(float* __restrict__ out) {
    const int tid  = threadIdx.x;
    const int warp = tid >> 5;
    const int lane = tid & 31;
    __shared__ float red[32];

    // 1024 threads x 2 batches: both loads issue immediately (high MLP),
    // then two independent log chains -- pure latency, ~one L2 round trip.
    float2 p0 = g_part[tid];
    float2 p1 = g_part[tid + 1024];
    float s = -(p0.y - 1.0f - __logf(p0.x))
            + -(p1.y - 1.0f - __logf(p1.x));

    #pragma unroll
    for (int o = 16; o; o >>= 1) s += __shfl_down_sync(0xffffffffu, s, o);
    if (lane == 0) red[warp] = s;
    __syncthreads();
    if (warp == 0) {
        float v = red[lane];
        #pragma unroll
        for (int o = 16; o; o >>= 1) v += __shfl_down_sync(0xffffffffu, v, o);
        if (lane == 0) *out = v / (float)B_SZ;
    }
}

extern "C" void kernel_launch(void* const* d_in, const int* in_sizes, int n_in,
                              void* d_out, int out_size) {
    const float* anchor    = (const float*)d_in[0];
    const float* positives = (const float*)d_in[1];
    const float* negatives = (const float*)d_in[2];
    float* out = (float*)d_out;

    contrastive_sim_kernel<<<B_SZ, THREADS>>>(anchor, positives, negatives);
    contrastive_reduce_kernel<<<1, 1024>>>(out);
}